// round 15
// baseline (speedup 1.0000x reference)
#include <cuda_runtime.h>
#include <cuda_bf16.h>
#include <math.h>
#include <stdint.h>

// MultiResolutionHashGrid: N=1e6, L=16, T=2^19, F=2.
// R15 = R14 body with 192-thread CTAs, 2 CTAs/SM (__launch_bounds__(192,2)
// caps regs at 170 -> 12 warps/SM vs 10). Same x-pair-merge branchless gather
// + smem-staged coalesced stores; kernel is at the 96-lines/point floor, this
// targets the last latency-hiding slack.

#define L_LEVELS 16
#define T_SIZE   524288u          // 2^19
#define T_MASK   (T_SIZE - 1u)
#define P1 2654435761u
#define P2 805459861u

#define BLOCK 192

struct ResArr { float r[L_LEVELS]; };

// Predicated non-coherent float2 load: no memory work when pred==0.
__device__ __forceinline__ float2 ldg_pred(const float2* p, uint32_t pred) {
    float2 r;
    asm("{\n\t"
        ".reg .pred p;\n\t"
        "setp.ne.u32 p, %2, 0;\n\t"
        "@p ld.global.nc.v2.f32 {%0, %1}, [%3];\n\t"
        "}"
        : "=f"(r.x), "=f"(r.y) : "r"(pred), "l"(p));
    return r;
}

__global__ __launch_bounds__(BLOCK, 2)
void hashgrid_kernel(const float* __restrict__ pos,
                     const float* __restrict__ table,
                     float4* __restrict__ out4,
                     int N, ResArr res)
{
    // BLOCK threads x (8 data + 1 pad) float4 = 27.6 KB/CTA; pad keeps the
    // LDS.128 flush conflict-free (row stride 36 floats). 2 CTAs/SM -> 55 KB.
    __shared__ float4 sm[BLOCK][9];

    const int t    = threadIdx.x;
    const int lane = t & 31;
    const int wrow = t & ~31;
    const int n    = blockIdx.x * BLOCK + t;

    if (n < N) {
        const float HI = 1.0f - 1e-6f;
        float px = pos[3 * n + 0];
        float py = pos[3 * n + 1];
        float pz = pos[3 * n + 2];
        // normalized = clip((p + 1) / 2.0, 0, 1-1e-6)   (2+1e-8 == 2.0f in f32)
        float nx = fminf(fmaxf((px + 1.0f) * 0.5f, 0.0f), HI);
        float ny = fminf(fmaxf((py + 1.0f) * 0.5f, 0.0f), HI);
        float nz = fminf(fmaxf((pz + 1.0f) * 0.5f, 0.0f), HI);

        const float2* tbl2 = reinterpret_cast<const float2*>(table);
        float2* mysm = reinterpret_cast<float2*>(&sm[t][0]);

        #pragma unroll
        for (int l = 0; l < L_LEVELS; ++l) {
            float rr = res.r[l];
            float sx = nx * rr, sy = ny * rr, sz = nz * rr;
            float fx0 = floorf(sx), fy0 = floorf(sy), fz0 = floorf(sz);
            float fx = sx - fx0, fy = sy - fy0, fz = sz - fz0;

            uint32_t cx = (uint32_t)(int32_t)fx0;
            uint32_t cy = (uint32_t)(int32_t)fy0;
            uint32_t cz = (uint32_t)(int32_t)fz0;

            uint32_t x0 = cx;            // x prime is 1
            uint32_t x1 = cx + 1u;
            uint32_t y0 = cy * P1;
            uint32_t y1 = y0 + P1;
            uint32_t z0 = cz * P2;
            uint32_t z1 = z0 + P2;

            const uint32_t oddx = cx & 1u;   // 1 -> need separate x1 load

            const float2* tl  = tbl2 + (size_t)l * T_SIZE;
            const float4* tl4 = reinterpret_cast<const float4*>(tl);

            float2 f000, f100, f001, f101, f010, f110, f011, f111;

            // For mixed hash m = yh ^ zh:
            //   i0 = (x0 ^ m) & MASK; float4 at i0>>1 holds {i0&~1, i0|1}.
            //   even x0: i1 = i0 ^ 1 -> other half of the same float4.
            //   odd  x0: i1 arbitrary -> predicated LDG.64.
            #define LOAD_PAIR(m, a, b)                                         \
            do {                                                               \
                uint32_t i0  = ((x0) ^ (m)) & T_MASK;                          \
                uint32_t i1  = ((x1) ^ (m)) & T_MASK;                          \
                float4  v  = __ldg(&tl4[i0 >> 1]);                             \
                float2  w  = ldg_pred(&tl[i1], oddx);                          \
                float2 lo2 = make_float2(v.x, v.y);                            \
                float2 hi2 = make_float2(v.z, v.w);                            \
                bool bit  = (i0 & 1u) != 0u;                                   \
                (a) = bit ? hi2 : lo2;                                         \
                float2 bev = bit ? lo2 : hi2;                                  \
                (b) = oddx ? w : bev;                                          \
            } while (0)

            LOAD_PAIR(y0 ^ z0, f000, f100);
            LOAD_PAIR(y0 ^ z1, f001, f101);
            LOAD_PAIR(y1 ^ z0, f010, f110);
            LOAD_PAIR(y1 ^ z1, f011, f111);
            #undef LOAD_PAIR

            float omz = 1.0f - fz;
            float c00x = f000.x * omz + f001.x * fz;
            float c00y = f000.y * omz + f001.y * fz;
            float c01x = f010.x * omz + f011.x * fz;
            float c01y = f010.y * omz + f011.y * fz;
            float c10x = f100.x * omz + f101.x * fz;
            float c10y = f100.y * omz + f101.y * fz;
            float c11x = f110.x * omz + f111.x * fz;
            float c11y = f110.y * omz + f111.y * fz;

            float omy = 1.0f - fy;
            float c0x = c00x * omy + c01x * fy;
            float c0y = c00y * omy + c01y * fy;
            float c1x = c10x * omy + c11x * fy;
            float c1y = c10y * omy + c11y * fy;

            float omx = 1.0f - fx;
            float2 o;
            o.x = c0x * omx + c1x * fx;
            o.y = c0y * omx + c1y * fx;
            mysm[l] = o;
        }
    }
    __syncwarp();

    // Coalesced flush: warp owns points [warpBase, warpBase+32) ->
    // out4 indices [warpBase*8, warpBase*8+256). 8 coalesced STG.128.
    const int warpBase = blockIdx.x * BLOCK + wrow;
    float4* dst = out4 + (size_t)warpBase * 8;
    #pragma unroll
    for (int j = 0; j < 8; ++j) {
        int idx = j * 32 + lane;
        int p = idx >> 3;            // point within warp
        int k = idx & 7;             // float4 index within point
        if (warpBase + p < N)
            dst[idx] = sm[wrow + p][k];
    }
}

extern "C" void kernel_launch(void* const* d_in, const int* in_sizes, int n_in,
                              void* d_out, int out_size)
{
    const float* positions   = (const float*)d_in[0];   // (N, 3)
    const float* hash_tables = (const float*)d_in[1];   // (L, T, F)
    float4* out = (float4*)d_out;                       // (N, 32 floats)

    int N = in_sizes[0] / 3;

    // Same double-precision libm sequence as the Python reference:
    // GROWTH = exp((log(2048)-log(16))/15); res_l = ceil(16*GROWTH**l).
    ResArr res;
    double growth = exp((log(2048.0) - log(16.0)) / 15.0);
    for (int l = 0; l < L_LEVELS; ++l) {
        res.r[l] = (float)ceil(16.0 * pow(growth, (double)l));
    }

    int blocks = (N + BLOCK - 1) / BLOCK;
    hashgrid_kernel<<<blocks, BLOCK>>>(positions, hash_tables, out, N, res);
}

// round 16
// speedup vs baseline: 1.0550x; 1.0550x over previous
#include <cuda_runtime.h>
#include <cuda_bf16.h>
#include <math.h>
#include <stdint.h>

// MultiResolutionHashGrid: N=1e6, L=16, T=2^19, F=2.
// FINAL (= R14, the measured best): x-pair-merge branchless gather
// (LDG.128 + predicated LDG.64; x hashes with prime 1 so even-x corner pairs
// share one aligned float4) + smem-staged warp-coalesced stores, 320-thread
// blocks -> 10 warps/SM. Kernel runs at the L1tex wavefront floor
// (~96 lines/point @ ~1 wf/cyc/SM); occupancy variants measured slower.

#define L_LEVELS 16
#define T_SIZE   524288u          // 2^19
#define T_MASK   (T_SIZE - 1u)
#define P1 2654435761u
#define P2 805459861u

#define BLOCK 320

struct ResArr { float r[L_LEVELS]; };

// Predicated non-coherent float2 load: no memory work when pred==0.
__device__ __forceinline__ float2 ldg_pred(const float2* p, uint32_t pred) {
    float2 r;
    asm("{\n\t"
        ".reg .pred p;\n\t"
        "setp.ne.u32 p, %2, 0;\n\t"
        "@p ld.global.nc.v2.f32 {%0, %1}, [%3];\n\t"
        "}"
        : "=f"(r.x), "=f"(r.y) : "r"(pred), "l"(p));
    return r;
}

__global__ __launch_bounds__(BLOCK, 1)
void hashgrid_kernel(const float* __restrict__ pos,
                     const float* __restrict__ table,
                     float4* __restrict__ out4,
                     int N, ResArr res)
{
    // BLOCK threads x (8 data + 1 pad) float4 = 46.1 KB; pad keeps flush
    // LDS.128 conflict-free (row stride 36 floats).
    __shared__ float4 sm[BLOCK][9];

    const int t    = threadIdx.x;
    const int lane = t & 31;
    const int wrow = t & ~31;
    const int n    = blockIdx.x * BLOCK + t;

    if (n < N) {
        const float HI = 1.0f - 1e-6f;
        float px = pos[3 * n + 0];
        float py = pos[3 * n + 1];
        float pz = pos[3 * n + 2];
        // normalized = clip((p + 1) / 2.0, 0, 1-1e-6)   (2+1e-8 == 2.0f in f32)
        float nx = fminf(fmaxf((px + 1.0f) * 0.5f, 0.0f), HI);
        float ny = fminf(fmaxf((py + 1.0f) * 0.5f, 0.0f), HI);
        float nz = fminf(fmaxf((pz + 1.0f) * 0.5f, 0.0f), HI);

        const float2* tbl2 = reinterpret_cast<const float2*>(table);
        float2* mysm = reinterpret_cast<float2*>(&sm[t][0]);

        #pragma unroll
        for (int l = 0; l < L_LEVELS; ++l) {
            float rr = res.r[l];
            float sx = nx * rr, sy = ny * rr, sz = nz * rr;
            float fx0 = floorf(sx), fy0 = floorf(sy), fz0 = floorf(sz);
            float fx = sx - fx0, fy = sy - fy0, fz = sz - fz0;

            uint32_t cx = (uint32_t)(int32_t)fx0;
            uint32_t cy = (uint32_t)(int32_t)fy0;
            uint32_t cz = (uint32_t)(int32_t)fz0;

            uint32_t x0 = cx;            // x prime is 1
            uint32_t x1 = cx + 1u;
            uint32_t y0 = cy * P1;
            uint32_t y1 = y0 + P1;
            uint32_t z0 = cz * P2;
            uint32_t z1 = z0 + P2;

            const uint32_t oddx = cx & 1u;   // 1 -> need separate x1 load

            const float2* tl  = tbl2 + (size_t)l * T_SIZE;
            const float4* tl4 = reinterpret_cast<const float4*>(tl);

            float2 f000, f100, f001, f101, f010, f110, f011, f111;

            // For mixed hash m = yh ^ zh:
            //   i0 = (x0 ^ m) & MASK; float4 at i0>>1 holds {i0&~1, i0|1}.
            //   even x0: i1 = i0 ^ 1 -> other half of the same float4.
            //   odd  x0: i1 arbitrary -> predicated LDG.64.
            #define LOAD_PAIR(m, a, b)                                         \
            do {                                                               \
                uint32_t i0  = ((x0) ^ (m)) & T_MASK;                          \
                uint32_t i1  = ((x1) ^ (m)) & T_MASK;                          \
                float4  v  = __ldg(&tl4[i0 >> 1]);                             \
                float2  w  = ldg_pred(&tl[i1], oddx);                          \
                float2 lo2 = make_float2(v.x, v.y);                            \
                float2 hi2 = make_float2(v.z, v.w);                            \
                bool bit  = (i0 & 1u) != 0u;                                   \
                (a) = bit ? hi2 : lo2;                                         \
                float2 bev = bit ? lo2 : hi2;                                  \
                (b) = oddx ? w : bev;                                          \
            } while (0)

            LOAD_PAIR(y0 ^ z0, f000, f100);
            LOAD_PAIR(y0 ^ z1, f001, f101);
            LOAD_PAIR(y1 ^ z0, f010, f110);
            LOAD_PAIR(y1 ^ z1, f011, f111);
            #undef LOAD_PAIR

            float omz = 1.0f - fz;
            float c00x = f000.x * omz + f001.x * fz;
            float c00y = f000.y * omz + f001.y * fz;
            float c01x = f010.x * omz + f011.x * fz;
            float c01y = f010.y * omz + f011.y * fz;
            float c10x = f100.x * omz + f101.x * fz;
            float c10y = f100.y * omz + f101.y * fz;
            float c11x = f110.x * omz + f111.x * fz;
            float c11y = f110.y * omz + f111.y * fz;

            float omy = 1.0f - fy;
            float c0x = c00x * omy + c01x * fy;
            float c0y = c00y * omy + c01y * fy;
            float c1x = c10x * omy + c11x * fy;
            float c1y = c10y * omy + c11y * fy;

            float omx = 1.0f - fx;
            float2 o;
            o.x = c0x * omx + c1x * fx;
            o.y = c0y * omx + c1y * fx;
            mysm[l] = o;
        }
    }
    __syncwarp();

    // Coalesced flush: warp owns points [warpBase, warpBase+32) ->
    // out4 indices [warpBase*8, warpBase*8+256). 8 coalesced STG.128.
    const int warpBase = blockIdx.x * BLOCK + wrow;
    float4* dst = out4 + (size_t)warpBase * 8;
    #pragma unroll
    for (int j = 0; j < 8; ++j) {
        int idx = j * 32 + lane;
        int p = idx >> 3;            // point within warp
        int k = idx & 7;             // float4 index within point
        if (warpBase + p < N)
            dst[idx] = sm[wrow + p][k];
    }
}

extern "C" void kernel_launch(void* const* d_in, const int* in_sizes, int n_in,
                              void* d_out, int out_size)
{
    const float* positions   = (const float*)d_in[0];   // (N, 3)
    const float* hash_tables = (const float*)d_in[1];   // (L, T, F)
    float4* out = (float4*)d_out;                       // (N, 32 floats)

    int N = in_sizes[0] / 3;

    // Same double-precision libm sequence as the Python reference:
    // GROWTH = exp((log(2048)-log(16))/15); res_l = ceil(16*GROWTH**l).
    ResArr res;
    double growth = exp((log(2048.0) - log(16.0)) / 15.0);
    for (int l = 0; l < L_LEVELS; ++l) {
        res.r[l] = (float)ceil(16.0 * pow(growth, (double)l));
    }

    int blocks = (N + BLOCK - 1) / BLOCK;
    hashgrid_kernel<<<blocks, BLOCK>>>(positions, hash_tables, out, N, res);
}

// round 17
// speedup vs baseline: 1.1081x; 1.0503x over previous
#include <cuda_runtime.h>
#include <cuda_bf16.h>
#include <math.h>
#include <stdint.h>

// MultiResolutionHashGrid: N=1e6, L=16, T=2^19, F=2.
// R17 = R14 body (x-pair-merge branchless gather + smem-staged coalesced
// stores, 320 thr / 1 CTA per SM) made persistent with WARP-LEVEL work
// stealing over 32-point chunks (atomic counter, next-chunk prefetch) to
// erase the ~15us tail-wave quantization of the 3125-CTA launch.

#define L_LEVELS 16
#define T_SIZE   524288u          // 2^19
#define T_MASK   (T_SIZE - 1u)
#define P1 2654435761u
#define P2 805459861u

#define BLOCK 320

struct ResArr { float r[L_LEVELS]; };

__device__ unsigned int g_chunk_counter;

__global__ void reset_counter_kernel() {
    g_chunk_counter = 0u;
}

// Predicated non-coherent float2 load: no memory work when pred==0.
__device__ __forceinline__ float2 ldg_pred(const float2* p, uint32_t pred) {
    float2 r;
    asm("{\n\t"
        ".reg .pred p;\n\t"
        "setp.ne.u32 p, %2, 0;\n\t"
        "@p ld.global.nc.v2.f32 {%0, %1}, [%3];\n\t"
        "}"
        : "=f"(r.x), "=f"(r.y) : "r"(pred), "l"(p));
    return r;
}

__global__ __launch_bounds__(BLOCK, 1)
void hashgrid_kernel(const float* __restrict__ pos,
                     const float* __restrict__ table,
                     float4* __restrict__ out4,
                     int N, int numChunks, ResArr res)
{
    // BLOCK threads x (8 data + 1 pad) float4 = 46.1 KB; pad keeps flush
    // LDS.128 conflict-free (row stride 36 floats).
    __shared__ float4 sm[BLOCK][9];

    const int t    = threadIdx.x;
    const int lane = t & 31;
    const int wrow = t & ~31;

    const float2* tbl2 = reinterpret_cast<const float2*>(table);
    float2* mysm = reinterpret_cast<float2*>(&sm[t][0]);
    const float HI = 1.0f - 1e-6f;

    // Warp grabs its first chunk.
    unsigned int cur = 0u;
    if (lane == 0) cur = atomicAdd(&g_chunk_counter, 1u);
    cur = __shfl_sync(0xFFFFFFFFu, cur, 0);

    while (cur < (unsigned int)numChunks) {
        // Prefetch next chunk id so the atomic round-trip hides under the body.
        unsigned int nxt = 0u;
        if (lane == 0) nxt = atomicAdd(&g_chunk_counter, 1u);
        nxt = __shfl_sync(0xFFFFFFFFu, nxt, 0);

        const int n = (int)(cur * 32u) + lane;   // this lane's point

        if (n < N) {
            float px = pos[3 * n + 0];
            float py = pos[3 * n + 1];
            float pz = pos[3 * n + 2];
            // normalized = clip((p + 1) / 2.0, 0, 1-1e-6)  (2+1e-8 == 2.0f)
            float nx = fminf(fmaxf((px + 1.0f) * 0.5f, 0.0f), HI);
            float ny = fminf(fmaxf((py + 1.0f) * 0.5f, 0.0f), HI);
            float nz = fminf(fmaxf((pz + 1.0f) * 0.5f, 0.0f), HI);

            #pragma unroll
            for (int l = 0; l < L_LEVELS; ++l) {
                float rr = res.r[l];
                float sx = nx * rr, sy = ny * rr, sz = nz * rr;
                float fx0 = floorf(sx), fy0 = floorf(sy), fz0 = floorf(sz);
                float fx = sx - fx0, fy = sy - fy0, fz = sz - fz0;

                uint32_t cx = (uint32_t)(int32_t)fx0;
                uint32_t cy = (uint32_t)(int32_t)fy0;
                uint32_t cz = (uint32_t)(int32_t)fz0;

                uint32_t x0 = cx;            // x prime is 1
                uint32_t x1 = cx + 1u;
                uint32_t y0 = cy * P1;
                uint32_t y1 = y0 + P1;
                uint32_t z0 = cz * P2;
                uint32_t z1 = z0 + P2;

                const uint32_t oddx = cx & 1u;

                const float2* tl  = tbl2 + (size_t)l * T_SIZE;
                const float4* tl4 = reinterpret_cast<const float4*>(tl);

                float2 f000, f100, f001, f101, f010, f110, f011, f111;

                // i0 = (x0^m)&MASK; float4 at i0>>1 holds {i0&~1, i0|1}.
                // even x0: partner is the other half of that float4.
                // odd  x0: predicated LDG.64 fetches the partner.
                #define LOAD_PAIR(m, a, b)                                     \
                do {                                                           \
                    uint32_t i0  = ((x0) ^ (m)) & T_MASK;                      \
                    uint32_t i1  = ((x1) ^ (m)) & T_MASK;                      \
                    float4  v  = __ldg(&tl4[i0 >> 1]);                         \
                    float2  w  = ldg_pred(&tl[i1], oddx);                      \
                    float2 lo2 = make_float2(v.x, v.y);                        \
                    float2 hi2 = make_float2(v.z, v.w);                        \
                    bool bit  = (i0 & 1u) != 0u;                               \
                    (a) = bit ? hi2 : lo2;                                     \
                    float2 bev = bit ? lo2 : hi2;                              \
                    (b) = oddx ? w : bev;                                      \
                } while (0)

                LOAD_PAIR(y0 ^ z0, f000, f100);
                LOAD_PAIR(y0 ^ z1, f001, f101);
                LOAD_PAIR(y1 ^ z0, f010, f110);
                LOAD_PAIR(y1 ^ z1, f011, f111);
                #undef LOAD_PAIR

                float omz = 1.0f - fz;
                float c00x = f000.x * omz + f001.x * fz;
                float c00y = f000.y * omz + f001.y * fz;
                float c01x = f010.x * omz + f011.x * fz;
                float c01y = f010.y * omz + f011.y * fz;
                float c10x = f100.x * omz + f101.x * fz;
                float c10y = f100.y * omz + f101.y * fz;
                float c11x = f110.x * omz + f111.x * fz;
                float c11y = f110.y * omz + f111.y * fz;

                float omy = 1.0f - fy;
                float c0x = c00x * omy + c01x * fy;
                float c0y = c00y * omy + c01y * fy;
                float c1x = c10x * omy + c11x * fy;
                float c1y = c10y * omy + c11y * fy;

                float omx = 1.0f - fx;
                float2 o;
                o.x = c0x * omx + c1x * fx;
                o.y = c0y * omx + c1y * fx;
                mysm[l] = o;
            }
        }
        __syncwarp();

        // Coalesced flush of this warp's 32-point chunk: out4 indices
        // [cur*32*8, cur*32*8 + 256). 8 coalesced STG.128.
        const int chunkBase = (int)(cur * 32u);
        float4* dst = out4 + (size_t)chunkBase * 8;
        #pragma unroll
        for (int j = 0; j < 8; ++j) {
            int idx = j * 32 + lane;
            int p = idx >> 3;            // point within chunk
            int k = idx & 7;             // float4 index within point
            if (chunkBase + p < N)
                dst[idx] = sm[wrow + p][k];
        }
        __syncwarp();

        cur = nxt;
    }
}

extern "C" void kernel_launch(void* const* d_in, const int* in_sizes, int n_in,
                              void* d_out, int out_size)
{
    const float* positions   = (const float*)d_in[0];   // (N, 3)
    const float* hash_tables = (const float*)d_in[1];   // (L, T, F)
    float4* out = (float4*)d_out;                       // (N, 32 floats)

    int N = in_sizes[0] / 3;
    int numChunks = (N + 31) / 32;

    // Same double-precision libm sequence as the Python reference:
    // GROWTH = exp((log(2048)-log(16))/15); res_l = ceil(16*GROWTH**l).
    ResArr res;
    double growth = exp((log(2048.0) - log(16.0)) / 15.0);
    for (int l = 0; l < L_LEVELS; ++l) {
        res.r[l] = (float)ceil(16.0 * pow(growth, (double)l));
    }

    int smCount = 148;
    cudaDeviceGetAttribute(&smCount, cudaDevAttrMultiProcessorCount, 0);

    reset_counter_kernel<<<1, 1>>>();
    hashgrid_kernel<<<smCount, BLOCK>>>(positions, hash_tables, out,
                                        N, numChunks, res);
}